// round 4
// baseline (speedup 1.0000x reference)
#include <cuda_runtime.h>
#include <cstdint>

// HolographicFMLayer: batched all-pairs circular convolution.
// inputs: float32 [B, 24, 64]  ->  out: float32 [B, 276, 64]
// out[b,p,n] = sum_k x[b,i,k] * x[b,j,(n-k) mod 64], pairs = triu_indices(24, k=1)
//
// CRT split: x^64-1 = (x^16-1)(x^16+1)(x^32+1)
//   per field: u = lo+hi, v = (lo-hi)/sqrt2; P=(u_lo+u_hi)/2, Q=(u_lo-u_hi)/2
//   per pair : d1 = cyclic16(P), d2 = negacyclic16(Q), c2 = negacyclic32(v)
//   recon    : c1[n<16]=d1+d2, c1[16..31]=d1-d2; out[n<32]=c1+c2, out[n+32]=c1-c2
// 1536 FMA/pair (vs 4096 direct), packed fma.rn.f32x2.
//
// R3: 2 threads per pair (role0: neg32 outs 0..15 + cyclic16; role1: neg32
// outs 16..31 + negacyclic16), shfl exchange, small blocks for occupancy.

#define NF 24
#define NPAIR 276
#define LEN 64
#define THREADS 192
#define PAIRS_PER_BLOCK 92      // 3 blocks per batch
#define ACTIVE (PAIRS_PER_BLOCK * 2)
#define SV 65                   // 64-entry rows, 65 mod 32 == 1
#define SP 33                   // 32-entry rows, 33 mod 32 == 1

__device__ __forceinline__ void ffma2(float2& d, float2 a, float2 b) {
    asm("fma.rn.f32x2 %0, %1, %2, %0;"
        : "+l"(*reinterpret_cast<unsigned long long*>(&d))
        : "l"(*reinterpret_cast<unsigned long long*>(&a)),
          "l"(*reinterpret_cast<unsigned long long*>(&b)));
}

// Partial length-N convolution: acc[q] = (out[QOFF+q], out[QOFF+q+8]), q=0..7,
// out[n] = sum_{k=0}^{N-1} A[k+N] * B[n-k+N].
// Sliding window: at iter k, w[q] = (B[QOFF+q+N-k], B[QOFF+q+8+N-k]).
// Shift reuses w[7].x as the new w[0].y -> 2 LDS per k (a + one window elem).
template <int N, int QOFF>
__device__ __forceinline__ void conv8(const float* __restrict__ A,
                                      const float* __restrict__ B,
                                      float2* __restrict__ acc)
{
#pragma unroll
    for (int q = 0; q < 8; ++q) acc[q] = make_float2(0.f, 0.f);
    float2 w[8];
#pragma unroll
    for (int q = 0; q < 8; ++q)
        w[q] = make_float2(B[QOFF + q + N], B[QOFF + q + 8 + N]);

#pragma unroll
    for (int k = 0; k < N; ++k) {
        const float a = A[k + N];
        const float2 aa = make_float2(a, a);
#pragma unroll
        for (int q = 0; q < 8; ++q) ffma2(acc[q], aa, w[q]);
        const float nw   = B[QOFF + N - 1 - k];   // >= QOFF >= 0: in-bounds
        const float keep = w[7].x;
#pragma unroll
        for (int q = 7; q > 0; --q) w[q] = w[q - 1];
        w[0] = make_float2(nw, keep);
    }
}

__global__ __launch_bounds__(THREADS, 5)
void holo_crt2_kernel(const float* __restrict__ in, float* __restrict__ out)
{
    __shared__ float bufV[NF * SV];  // negacyclic-32 operand, scale 1/sqrt2
    __shared__ float bufP[NF * SP];  // cyclic-16 operand (duplicated), scale 1/2
    __shared__ float bufQ[NF * SP];  // negacyclic-16 operand, scale 1/2

    const int batch = blockIdx.x;
    const float* __restrict__ src = in + (size_t)batch * (NF * LEN);

    // ---- per-field folds ----
    for (int idx = threadIdx.x; idx < NF * 16; idx += THREADS) {
        const int f = idx >> 4, m = idx & 15;
        const float* x = src + f * LEN;
        const float x0 = x[m], x1 = x[m + 16], x2 = x[m + 32], x3 = x[m + 48];
        const float s = 0.70710678118654752f;
        const float vlo = (x0 - x2) * s, vhi = (x1 - x3) * s;
        const float ulo = x0 + x2,       uhi = x1 + x3;
        const float P = (ulo + uhi) * 0.5f, Q = (ulo - uhi) * 0.5f;
        float* bV = bufV + f * SV;
        bV[m]      = -vlo;  bV[m + 16] = -vhi;
        bV[m + 32] =  vlo;  bV[m + 48] =  vhi;
        float* bP = bufP + f * SP;
        bP[m] = P;  bP[m + 16] = P;
        float* bQ = bufQ + f * SP;
        bQ[m] = -Q; bQ[m + 16] = Q;
    }
    __syncthreads();

    const int t = threadIdx.x;
    if (t >= ACTIVE) return;

    const int role = t & 1;                            // lanes 2p, 2p+1
    const int p    = blockIdx.y * PAIRS_PER_BLOCK + (t >> 1);

    // decode (i, j): row-major triu, k=1
    int i = 0, rem = p;
    while (rem >= NF - 1 - i) { rem -= NF - 1 - i; ++i; }
    const int j = i + 1 + rem;

    const float* Vi = bufV + i * SV;
    const float* Vj = bufV + j * SV;

    // negacyclic-32, split by role
    float2 av[8];
    if (role == 0) conv8<32, 0 >(Vi, Vj, av);  // av[q] = (c2[q],    c2[q+8])
    else           conv8<32, 16>(Vi, Vj, av);  // av[q] = (c2[16+q], c2[24+q])

    // one 16-conv each: role0 -> cyclic (P), role1 -> negacyclic (Q)
    const float* Ai = (role ? bufQ : bufP) + i * SP;
    const float* Aj = (role ? bufQ : bufP) + j * SP;
    float2 dmine[8];
    conv8<16, 0>(Ai, Aj, dmine);               // dmine[q] = (d[q], d[q+8])

    // exchange d-vectors between the two role threads (adjacent lanes)
    float2 dother[8];
#pragma unroll
    for (int q = 0; q < 8; ++q) {
        unsigned long long v = *reinterpret_cast<unsigned long long*>(&dmine[q]);
        v = __shfl_xor_sync(0xFFFFFFFFu, v, 1);
        *reinterpret_cast<unsigned long long*>(&dother[q]) = v;
    }

    // role0: d1 = mine, d2 = other, c1 = d1 + d2 (n mod 16 in 0..15)
    // role1: d1 = other, d2 = mine, c1 = d1 - d2 (n in 16..31)
    float r0[8], r1[8], r2[8], r3[8];   // out[base..+7], [base+8..], [base+32..], [base+40..]
#pragma unroll
    for (int q = 0; q < 8; ++q) {
        float c1x, c1y;
        if (role == 0) { c1x = dmine[q].x + dother[q].x; c1y = dmine[q].y + dother[q].y; }
        else           { c1x = dother[q].x - dmine[q].x; c1y = dother[q].y - dmine[q].y; }
        r0[q] = c1x + av[q].x;
        r1[q] = c1y + av[q].y;
        r2[q] = c1x - av[q].x;
        r3[q] = c1y - av[q].y;
    }

    const int base = role << 4;  // 0 or 16
    float4* __restrict__ dst =
        (float4*)(out + ((size_t)batch * NPAIR + p) * LEN + base);
    dst[0]  = make_float4(r0[0], r0[1], r0[2], r0[3]);
    dst[1]  = make_float4(r0[4], r0[5], r0[6], r0[7]);
    dst[2]  = make_float4(r1[0], r1[1], r1[2], r1[3]);
    dst[3]  = make_float4(r1[4], r1[5], r1[6], r1[7]);
    dst[8]  = make_float4(r2[0], r2[1], r2[2], r2[3]);
    dst[9]  = make_float4(r2[4], r2[5], r2[6], r2[7]);
    dst[10] = make_float4(r3[0], r3[1], r3[2], r3[3]);
    dst[11] = make_float4(r3[4], r3[5], r3[6], r3[7]);
}

extern "C" void kernel_launch(void* const* d_in, const int* in_sizes, int n_in,
                              void* d_out, int out_size)
{
    const float* in  = (const float*)d_in[0];
    float*       out = (float*)d_out;
    const int batches = in_sizes[0] / (NF * LEN);   // 2048 for the bench shape
    dim3 grid(batches, 3);
    holo_crt2_kernel<<<grid, THREADS>>>(in, out);
}